// round 5
// baseline (speedup 1.0000x reference)
#include <cuda_runtime.h>

// Problem constants (fixed by the dataset)
#define Nn 8
#define Kk 16
#define Hh 256
#define Ww 256
#define Cc 4
#define Pp 100000
#define HW (Hh * Ww)          // 65536
#define NPIX (Nn * HW)        // 524288

// Scratch: ptclds transposed to AoS (P x float4) — __device__ global, no alloc.
__device__ float4 g_ptcld_aos[Pp];

// Kernel 1: transpose (C,P) -> AoS float4[P]
__global__ void transpose_ptcld_kernel(const float* __restrict__ ptclds) {
    int i = blockIdx.x * blockDim.x + threadIdx.x;
    if (i < Pp) {
        float4 v;
        v.x = ptclds[0 * Pp + i];
        v.y = ptclds[1 * Pp + i];
        v.z = ptclds[2 * Pp + i];
        v.w = ptclds[3 * Pp + i];
        g_ptcld_aos[i] = v;
    }
}

// Kernel 2: 1 thread per pixel. ALL k-slot loads issued up front (MLP ~32),
// gathers predicated per slot, second half skipped when the z-sorted
// sentinel says no more points.
__global__ __launch_bounds__(256) void composite_kernel(
    const int*   __restrict__ fragments,   // (N,K,H,W)
    const float* __restrict__ alphas,      // (N,K,H,W)
    const float* __restrict__ background,  // (3,)
    float*       __restrict__ out)         // (N,C,H,W)
{
    int pix = blockIdx.x * blockDim.x + threadIdx.x;
    int n  = pix >> 16;          // pix / HW
    int hw = pix & (HW - 1);     // pix % HW

    const int base = n * (Kk * HW) + hw;
    float* outp = out + n * (Cc * HW) + hw;

    // Issue ALL input loads back-to-back: 32 independent coalesced LDGs.
    int   f[Kk];
    float a[Kk];
    #pragma unroll
    for (int k = 0; k < Kk; ++k) f[k] = fragments[base + k * HW];
    #pragma unroll
    for (int k = 0; k < Kk; ++k) a[k] = alphas[base + k * HW];

    float T = 1.f, r = 0.f, g = 0.f, b = 0.f, acc = 0.f;

    // ---- half 1: k = 0..7 ----
    {
        float4 p[8];
        #pragma unroll
        for (int j = 0; j < 8; ++j)
            if (f[j] >= 0) p[j] = g_ptcld_aos[f[j]];
        #pragma unroll
        for (int j = 0; j < 8; ++j) {
            if (f[j] >= 0) {
                float w = a[j] * T;  T *= (1.0f - a[j]);
                r   = fmaf(w, p[j].x, r);
                g   = fmaf(w, p[j].y, g);
                b   = fmaf(w, p[j].z, b);
                acc = fmaf(w, p[j].w, acc);
            }
        }
    }

    // ---- half 2: k = 8..15 (skip entirely if the z-sorted sentinel hit) ----
    if (f[7] >= 0) {
        float4 p[8];
        #pragma unroll
        for (int j = 0; j < 8; ++j)
            if (f[8 + j] >= 0) p[j] = g_ptcld_aos[f[8 + j]];
        #pragma unroll
        for (int j = 0; j < 8; ++j) {
            int k = 8 + j;
            if (f[k] >= 0) {
                float w = a[k] * T;  T *= (1.0f - a[k]);
                r   = fmaf(w, p[j].x, r);
                g   = fmaf(w, p[j].y, g);
                b   = fmaf(w, p[j].z, b);
                acc = fmaf(w, p[j].w, acc);
            }
        }
    }

    // Background fill where no nearest point exists
    if (f[0] < 0) {
        r = background[0]; g = background[1]; b = background[2]; acc = 1.0f;
    }

    outp[0 * HW] = r;
    outp[1 * HW] = g;
    outp[2 * HW] = b;
    outp[3 * HW] = acc;
}

extern "C" void kernel_launch(void* const* d_in, const int* in_sizes, int n_in,
                              void* d_out, int out_size) {
    const int*   fragments  = (const int*)  d_in[0];  // (N,K,H,W) int32
    const float* alphas     = (const float*)d_in[1];  // (N,K,H,W) f32
    const float* ptclds     = (const float*)d_in[2];  // (C,P) f32
    const float* background = (const float*)d_in[3];  // (3,) f32
    float* out = (float*)d_out;                       // (N,C,H,W) f32

    transpose_ptcld_kernel<<<(Pp + 255) / 256, 256>>>(ptclds);
    composite_kernel<<<NPIX / 256, 256>>>(fragments, alphas, background, out);
}

// round 7
// speedup vs baseline: 1.1504x; 1.1504x over previous
#include <cuda_runtime.h>

// Problem constants (fixed by the dataset)
#define Nn 8
#define Kk 16
#define Hh 256
#define Ww 256
#define Cc 4
#define Pp 100000
#define HW (Hh * Ww)          // 65536
#define NPIX (Nn * HW)        // 524288

// Scratch: ptclds transposed to AoS (P x float4) — __device__ global, no alloc.
__device__ float4 g_ptcld_aos[Pp];

// Kernel 1: transpose (C,P) -> AoS float4[P]
__global__ void transpose_ptcld_kernel(const float* __restrict__ ptclds) {
    int i = blockIdx.x * blockDim.x + threadIdx.x;
    if (i < Pp) {
        float4 v;
        v.x = ptclds[0 * Pp + i];
        v.y = ptclds[1 * Pp + i];
        v.z = ptclds[2 * Pp + i];
        v.w = ptclds[3 * Pp + i];
        g_ptcld_aos[i] = v;
    }
}

// Kernel 2: 1 thread per pixel. launch_bounds(256,2) -> 128-reg budget so
// ptxas can ACTUALLY front-batch all 32 input LDGs + 8-wide gather batches
// (round-5 failure: default heuristic chose 58 regs and serialized them).
__global__ __launch_bounds__(256, 2) void composite_kernel(
    const int*   __restrict__ fragments,   // (N,K,H,W)
    const float* __restrict__ alphas,      // (N,K,H,W)
    const float* __restrict__ background,  // (3,)
    float*       __restrict__ out)         // (N,C,H,W)
{
    int pix = blockIdx.x * blockDim.x + threadIdx.x;
    int n  = pix >> 16;          // pix / HW
    int hw = pix & (HW - 1);     // pix % HW

    const int base = n * (Kk * HW) + hw;
    float* outp = out + n * (Cc * HW) + hw;

    // Batch 1: all 16 fragment loads (gather addresses depend on these).
    int f[Kk];
    #pragma unroll
    for (int k = 0; k < Kk; ++k) f[k] = fragments[base + k * HW];

    // Batch 2: all 16 alpha loads — independent, overlap with everything.
    float a[Kk];
    #pragma unroll
    for (int k = 0; k < Kk; ++k) a[k] = alphas[base + k * HW];

    float T = 1.f, r = 0.f, g = 0.f, b = 0.f, acc = 0.f;

    // ---- half 1: k = 0..7 : 8 predicated gathers batched, then math ----
    {
        float4 p[8];
        #pragma unroll
        for (int j = 0; j < 8; ++j)
            if (f[j] >= 0) p[j] = g_ptcld_aos[f[j]];
        #pragma unroll
        for (int j = 0; j < 8; ++j) {
            if (f[j] >= 0) {
                float w = a[j] * T;  T *= (1.0f - a[j]);
                r   = fmaf(w, p[j].x, r);
                g   = fmaf(w, p[j].y, g);
                b   = fmaf(w, p[j].z, b);
                acc = fmaf(w, p[j].w, acc);
            }
        }
    }

    // ---- half 2: k = 8..15 (skip entirely if the z-sorted sentinel hit) ----
    if (f[7] >= 0) {
        float4 p[8];
        #pragma unroll
        for (int j = 0; j < 8; ++j)
            if (f[8 + j] >= 0) p[j] = g_ptcld_aos[f[8 + j]];
        #pragma unroll
        for (int j = 0; j < 8; ++j) {
            int k = 8 + j;
            if (f[k] >= 0) {
                float w = a[k] * T;  T *= (1.0f - a[k]);
                r   = fmaf(w, p[j].x, r);
                g   = fmaf(w, p[j].y, g);
                b   = fmaf(w, p[j].z, b);
                acc = fmaf(w, p[j].w, acc);
            }
        }
    }

    // Background fill where no nearest point exists
    if (f[0] < 0) {
        r = background[0]; g = background[1]; b = background[2]; acc = 1.0f;
    }

    outp[0 * HW] = r;
    outp[1 * HW] = g;
    outp[2 * HW] = b;
    outp[3 * HW] = acc;
}

extern "C" void kernel_launch(void* const* d_in, const int* in_sizes, int n_in,
                              void* d_out, int out_size) {
    const int*   fragments  = (const int*)  d_in[0];  // (N,K,H,W) int32
    const float* alphas     = (const float*)d_in[1];  // (N,K,H,W) f32
    const float* ptclds     = (const float*)d_in[2];  // (C,P) f32
    const float* background = (const float*)d_in[3];  // (3,) f32
    float* out = (float*)d_out;                       // (N,C,H,W) f32

    transpose_ptcld_kernel<<<(Pp + 255) / 256, 256>>>(ptclds);
    composite_kernel<<<NPIX / 256, 256>>>(fragments, alphas, background, out);
}